// round 9
// baseline (speedup 1.0000x reference)
#include <cuda_runtime.h>
#include <cuda_bf16.h>
#include <math.h>
#include <stdint.h>

#define D    256
#define DL   256
#define S    2048
#define B    8
#define F    8192
#define NE   (B * F)
#define MAXIT (2 * NE)
#define TAB_PRED 2048
#define TAB_ROLE 3072
#define TAB_ROWS 3138
#define STAGE_PITCH 132
#define PITCH_B 80              // padded row pitch (bytes) for 32-bf16 k-chunk rows
#define MAT_BYTES (128 * PITCH_B)          // 10240
#define STAGE_BYTES (4 * MAT_BYTES)        // X hi/lo + W hi/lo = 40960
#define DYN_SMEM (2 * STAGE_BYTES)         // 81920 (2 stages); epilogue 67584 fits

// ---------------- device scratch ----------------
__device__ float g_agg[B * S * D];
__device__ float g_pooled[B * D];
__device__ int   g_items[MAXIT];
__device__ int   g_count;
__device__ __align__(16) __nv_bfloat16 g_tabh[TAB_ROWS * 256];
__device__ __align__(16) __nv_bfloat16 g_tabl[TAB_ROWS * 256];
__device__ __align__(16) __nv_bfloat16 g_w1th[512 * 768];   // W1^T [n][k]
__device__ __align__(16) __nv_bfloat16 g_w1tl[512 * 768];
__device__ __align__(16) __nv_bfloat16 g_w2th[256 * 512];   // W2^T [n][k]
__device__ __align__(16) __nv_bfloat16 g_w2tl[256 * 512];
__device__ __align__(16) __nv_bfloat16 g_Hh[(size_t)MAXIT * 512];
__device__ __align__(16) __nv_bfloat16 g_Hl[(size_t)MAXIT * 512];

__device__ __forceinline__ uint32_t smem_u32_of(const void* p) {
    uint32_t a;
    asm("{ .reg .u64 t; cvta.to.shared.u64 t, %1; cvt.u32.u64 %0, t; }" : "=r"(a) : "l"(p));
    return a;
}
__device__ __forceinline__ float gelu_e(float x) { return x * normcdff(x); }

#define LDSM4(r0, r1, r2, r3, addr) \
    asm volatile("ldmatrix.sync.aligned.m8n8.x4.shared.b16 {%0,%1,%2,%3}, [%4];" \
        : "=r"(r0), "=r"(r1), "=r"(r2), "=r"(r3) : "r"(addr))

#define MMA16816(c, a, b0, b1) \
    asm volatile("mma.sync.aligned.m16n8k16.row.col.f32.bf16.bf16.f32 " \
        "{%0,%1,%2,%3}, {%4,%5,%6,%7}, {%8,%9}, {%0,%1,%2,%3};" \
        : "+f"((c)[0]), "+f"((c)[1]), "+f"((c)[2]), "+f"((c)[3]) \
        : "r"((a)[0]), "r"((a)[1]), "r"((a)[2]), "r"((a)[3]), "r"(b0), "r"(b1))

#define CP16(dst, src) \
    asm volatile("cp.async.cg.shared.global [%0], [%1], 16;" \
        :: "r"(dst), "l"(__cvta_generic_to_global(src)) : "memory")
#define CP_COMMIT() asm volatile("cp.async.commit_group;" ::: "memory")
#define CP_WAIT1()  asm volatile("cp.async.wait_group 1;" ::: "memory")

// ---------------- zero ----------------
__global__ void zero_kernel() {
    int i = blockIdx.x * blockDim.x + threadIdx.x;
    if (i < B * S * D) g_agg[i] = 0.0f;
    if (i < B * D)     g_pooled[i] = 0.0f;
    if (i == 0)        g_count = 0;
}

// ---------------- compact ----------------
__global__ void compact_kernel(const int* __restrict__ mask, const int* __restrict__ is_role,
                               const int* __restrict__ add_rev) {
    int e = blockIdx.x * blockDim.x + threadIdx.x;
    if (e >= NE) return;
    if (!mask[e]) return;
    bool rev = (!is_role[e]) && add_rev[e];
    int slot = atomicAdd(&g_count, rev ? 2 : 1);
    g_items[slot] = e << 1;
    if (rev) g_items[slot + 1] = (e << 1) | 1;
}

// ---------------- prep: split tables + W^T hi/lo ----------------
__global__ void prep_kernel(const float* __restrict__ pos, const float* __restrict__ pred,
                            const float* __restrict__ role,
                            const float* __restrict__ w1, const float* __restrict__ w2) {
    int tid = blockIdx.x * blockDim.x + threadIdx.x;
    const int NTAB = TAB_ROWS * 256;
    const int NW1 = 512 * 768;
    const int NW2 = 256 * 512;
    if (tid < NTAB) {
        int row = tid >> 8, col = tid & 255;
        float v;
        if (row < TAB_PRED)      v = pos[tid];
        else if (row < TAB_ROLE) v = pred[(row - TAB_PRED) * 256 + col];
        else                     v = role[(row - TAB_ROLE) * 256 + col];
        __nv_bfloat16 h = __float2bfloat16(v);
        g_tabh[tid] = h;
        g_tabl[tid] = __float2bfloat16(v - __bfloat162float(h));
    } else if (tid < NTAB + NW1) {
        int u = tid - NTAB;                    // u = n*768 + k
        int n = u / 768, k = u - n * 768;
        float v = w1[(size_t)k * 512 + n];
        __nv_bfloat16 h = __float2bfloat16(v);
        g_w1th[u] = h;
        g_w1tl[u] = __float2bfloat16(v - __bfloat162float(h));
    } else if (tid < NTAB + NW1 + NW2) {
        int u = tid - NTAB - NW1;              // u = n*512 + k
        int n = u / 512, k = u - n * 512;
        float v = w2[(size_t)k * 256 + n];
        __nv_bfloat16 h = __float2bfloat16(v);
        g_w2th[u] = h;
        g_w2tl[u] = __float2bfloat16(v - __bfloat162float(h));
    }
}

// ---------------- GEMM1: X[128x768] @ W1[768x512] -> gelu -> g_H ----------------
// grid = tiles x 4 n-quarters; 256 thr; warp tile 32(M) x 64(N); cp.async 2-stage
__global__ void __launch_bounds__(256, 2)
gemm1_kernel(const int* __restrict__ pred_idx,
             const int* __restrict__ a0, const int* __restrict__ a1,
             const int* __restrict__ role_idx, const int* __restrict__ is_role,
             const float* __restrict__ b1) {
    extern __shared__ char smraw[];
    __shared__ int ssrc[128][3];

    int t = threadIdx.x;
    int tile = blockIdx.x >> 2, nq = blockIdx.x & 3;
    int count = g_count;
    int base = tile * 128;
    if (base >= count) return;
    int nE = min(128, count - base);

    if (t < 128) {
        int r0 = 0, r1 = TAB_PRED, r2 = 0;
        if (t < nE) {
            int item = g_items[base + t];
            int e = item >> 1, dir = item & 1;
            int i0 = a0[e], i1 = a1[e];
            r1 = TAB_PRED + pred_idx[e];
            if (dir == 0) {
                int rr = is_role[e];
                r0 = i0;
                r2 = rr ? (TAB_ROLE + role_idx[e]) : i1;
            } else { r0 = i1; r2 = i0; }
        }
        ssrc[t][0] = r0; ssrc[t][1] = r1; ssrc[t][2] = r2;
    }
    __syncthreads();

    uint32_t smu = smem_u32_of(smraw);
    int w = t >> 5, lane = t & 31;
    int wm = w >> 1, wn = w & 1;
    int blk = lane >> 3, brow = lane & 7;

    float acc[64];
    #pragma unroll
    for (int i = 0; i < 64; i++) acc[i] = 0.0f;

    const int KC = 24;  // 768 / 32

    // fill lambda (macro-style): chunk kc into stage st
    #define G1_FILL(kc_, st_) do { \
        uint32_t sb = smu + (st_) * STAGE_BYTES; \
        int seg_ = (kc_) >> 3; \
        int inner_ = ((kc_) & 7) * 64; \
        _Pragma("unroll") \
        for (int i = t; i < 1024; i += 256) { \
            int half_ = i >> 9, j_ = i & 511, e_ = j_ >> 2, q_ = j_ & 3; \
            const char* src_ = (half_ ? (const char*)g_tabl : (const char*)g_tabh) \
                               + (size_t)ssrc[e_][seg_] * 512 + inner_ + q_ * 16; \
            CP16(sb + half_ * MAT_BYTES + e_ * PITCH_B + q_ * 16, src_); \
        } \
        _Pragma("unroll") \
        for (int i = t; i < 1024; i += 256) { \
            int half_ = i >> 9, j_ = i & 511, r_ = j_ >> 2, q_ = j_ & 3; \
            const char* src_ = (half_ ? (const char*)g_w1tl : (const char*)g_w1th) \
                               + (size_t)(nq * 128 + r_) * 1536 + (kc_) * 64 + q_ * 16; \
            CP16(sb + 2 * MAT_BYTES + half_ * MAT_BYTES + r_ * PITCH_B + q_ * 16, src_); \
        } \
    } while (0)

    G1_FILL(0, 0);
    CP_COMMIT();

    for (int kc = 0; kc < KC; kc++) {
        __syncthreads();                    // buffer (kc+1)&1 no longer read by MMA(kc-1)
        if (kc + 1 < KC) G1_FILL(kc + 1, (kc + 1) & 1);
        CP_COMMIT();
        CP_WAIT1();
        __syncthreads();

        uint32_t sb = smu + (kc & 1) * STAGE_BYTES;
        uint32_t xh_u = sb, xl_u = sb + MAT_BYTES;
        uint32_t wh_u = sb + 2 * MAT_BYTES, wl_u = sb + 3 * MAT_BYTES;

        #pragma unroll
        for (int kk = 0; kk < 2; kk++) {
            uint32_t ah[2][4], al[2][4];
            #pragma unroll
            for (int mf = 0; mf < 2; mf++) {
                uint32_t off = (uint32_t)(wm * 32 + mf * 16 + (blk & 1) * 8 + brow) * PITCH_B
                               + kk * 32 + (blk >> 1) * 16;
                LDSM4(ah[mf][0], ah[mf][1], ah[mf][2], ah[mf][3], xh_u + off);
                LDSM4(al[mf][0], al[mf][1], al[mf][2], al[mf][3], xl_u + off);
            }
            #pragma unroll
            for (int nf2 = 0; nf2 < 4; nf2++) {
                uint32_t boff = (uint32_t)(wn * 64 + nf2 * 16 + (blk >> 1) * 8 + brow) * PITCH_B
                                + kk * 32 + (blk & 1) * 16;
                uint32_t bh[4], bl[4];
                LDSM4(bh[0], bh[1], bh[2], bh[3], wh_u + boff);
                LDSM4(bl[0], bl[1], bl[2], bl[3], wl_u + boff);
                float* c0 = &acc[(nf2 * 2) * 4];
                float* c1 = &acc[(nf2 * 2 + 1) * 4];
                float* c2 = &acc[(8 + nf2 * 2) * 4];
                float* c3 = &acc[(8 + nf2 * 2 + 1) * 4];
                MMA16816(c0, ah[0], bh[0], bh[1]);
                MMA16816(c1, ah[0], bh[2], bh[3]);
                MMA16816(c2, ah[1], bh[0], bh[1]);
                MMA16816(c3, ah[1], bh[2], bh[3]);
                MMA16816(c0, ah[0], bl[0], bl[1]);
                MMA16816(c1, ah[0], bl[2], bl[3]);
                MMA16816(c2, ah[1], bl[0], bl[1]);
                MMA16816(c3, ah[1], bl[2], bl[3]);
                MMA16816(c0, al[0], bh[0], bh[1]);
                MMA16816(c1, al[0], bh[2], bh[3]);
                MMA16816(c2, al[1], bh[0], bh[1]);
                MMA16816(c3, al[1], bh[2], bh[3]);
            }
        }
    }
    __syncthreads();

    // stage accumulators -> bias+gelu+split -> g_H
    float* stage = (float*)smraw;
    int g = lane >> 2, i2 = (lane & 3) * 2;
    #pragma unroll
    for (int mf = 0; mf < 2; mf++)
        #pragma unroll
        for (int nf = 0; nf < 8; nf++) {
            float* c = &acc[(mf * 8 + nf) * 4];
            int r = wm * 32 + mf * 16 + g;
            int col = wn * 64 + nf * 8 + i2;
            stage[r * STAGE_PITCH + col]     = c[0];
            stage[r * STAGE_PITCH + col + 1] = c[1];
            stage[(r + 8) * STAGE_PITCH + col]     = c[2];
            stage[(r + 8) * STAGE_PITCH + col + 1] = c[3];
        }
    __syncthreads();
    {
        int col = t & 127, eh = t >> 7;
        float bias = b1[nq * 128 + col];
        for (int e = eh; e < nE; e += 2) {
            float x = stage[e * STAGE_PITCH + col] + bias;
            float y = gelu_e(x);
            __nv_bfloat16 h = __float2bfloat16(y);
            size_t o = (size_t)(base + e) * 512 + nq * 128 + col;
            g_Hh[o] = h;
            g_Hl[o] = __float2bfloat16(y - __bfloat162float(h));
        }
    }
}

// ---------------- GEMM2: H[128x512] @ W2[512x256] -> +b2 -> atomic scatter ----------------
__global__ void __launch_bounds__(256, 2)
gemm2_kernel(const int* __restrict__ a0, const int* __restrict__ a1,
             const int* __restrict__ is_role, const float* __restrict__ b2) {
    extern __shared__ char smraw[];
    __shared__ int stgt[128];

    int t = threadIdx.x;
    int tile = blockIdx.x >> 1, nq = blockIdx.x & 1;
    int count = g_count;
    int base = tile * 128;
    if (base >= count) return;
    int nE = min(128, count - base);

    if (t < 128) {
        int tg = 0, bidx = 0;
        if (t < nE) {
            int item = g_items[base + t];
            int e = item >> 1, dir = item & 1;
            bidx = e >> 13;
            int i0 = a0[e], i1 = a1[e];
            if (dir == 0) { int rr = is_role[e]; tg = rr ? i0 : i1; }
            else tg = i0;
        }
        stgt[t] = (bidx * S + tg) * D;
    }
    __syncthreads();

    uint32_t smu = smem_u32_of(smraw);
    int w = t >> 5, lane = t & 31;
    int wm = w >> 1, wn = w & 1;
    int blk = lane >> 3, brow = lane & 7;

    float acc[64];
    #pragma unroll
    for (int i = 0; i < 64; i++) acc[i] = 0.0f;

    const int KC = 16;  // 512 / 32

    #define G2_FILL(kc_, st_) do { \
        uint32_t sb = smu + (st_) * STAGE_BYTES; \
        _Pragma("unroll") \
        for (int i = t; i < 1024; i += 256) { \
            int half_ = i >> 9, j_ = i & 511, e_ = j_ >> 2, q_ = j_ & 3; \
            const char* src_ = (half_ ? (const char*)g_Hl : (const char*)g_Hh) \
                               + (size_t)(base + e_) * 1024 + (kc_) * 64 + q_ * 16; \
            CP16(sb + half_ * MAT_BYTES + e_ * PITCH_B + q_ * 16, src_); \
        } \
        _Pragma("unroll") \
        for (int i = t; i < 1024; i += 256) { \
            int half_ = i >> 9, j_ = i & 511, r_ = j_ >> 2, q_ = j_ & 3; \
            const char* src_ = (half_ ? (const char*)g_w2tl : (const char*)g_w2th) \
                               + (size_t)(nq * 128 + r_) * 1024 + (kc_) * 64 + q_ * 16; \
            CP16(sb + 2 * MAT_BYTES + half_ * MAT_BYTES + r_ * PITCH_B + q_ * 16, src_); \
        } \
    } while (0)

    G2_FILL(0, 0);
    CP_COMMIT();

    for (int kc = 0; kc < KC; kc++) {
        __syncthreads();
        if (kc + 1 < KC) G2_FILL(kc + 1, (kc + 1) & 1);
        CP_COMMIT();
        CP_WAIT1();
        __syncthreads();

        uint32_t sb = smu + (kc & 1) * STAGE_BYTES;
        uint32_t xh_u = sb, xl_u = sb + MAT_BYTES;
        uint32_t wh_u = sb + 2 * MAT_BYTES, wl_u = sb + 3 * MAT_BYTES;

        #pragma unroll
        for (int kk = 0; kk < 2; kk++) {
            uint32_t ah[2][4], al[2][4];
            #pragma unroll
            for (int mf = 0; mf < 2; mf++) {
                uint32_t off = (uint32_t)(wm * 32 + mf * 16 + (blk & 1) * 8 + brow) * PITCH_B
                               + kk * 32 + (blk >> 1) * 16;
                LDSM4(ah[mf][0], ah[mf][1], ah[mf][2], ah[mf][3], xh_u + off);
                LDSM4(al[mf][0], al[mf][1], al[mf][2], al[mf][3], xl_u + off);
            }
            #pragma unroll
            for (int nf2 = 0; nf2 < 4; nf2++) {
                uint32_t boff = (uint32_t)(wn * 64 + nf2 * 16 + (blk >> 1) * 8 + brow) * PITCH_B
                                + kk * 32 + (blk & 1) * 16;
                uint32_t bh[4], bl[4];
                LDSM4(bh[0], bh[1], bh[2], bh[3], wh_u + boff);
                LDSM4(bl[0], bl[1], bl[2], bl[3], wl_u + boff);
                float* c0 = &acc[(nf2 * 2) * 4];
                float* c1 = &acc[(nf2 * 2 + 1) * 4];
                float* c2 = &acc[(8 + nf2 * 2) * 4];
                float* c3 = &acc[(8 + nf2 * 2 + 1) * 4];
                MMA16816(c0, ah[0], bh[0], bh[1]);
                MMA16816(c1, ah[0], bh[2], bh[3]);
                MMA16816(c2, ah[1], bh[0], bh[1]);
                MMA16816(c3, ah[1], bh[2], bh[3]);
                MMA16816(c0, ah[0], bl[0], bl[1]);
                MMA16816(c1, ah[0], bl[2], bl[3]);
                MMA16816(c2, ah[1], bl[0], bl[1]);
                MMA16816(c3, ah[1], bl[2], bl[3]);
                MMA16816(c0, al[0], bh[0], bh[1]);
                MMA16816(c1, al[0], bh[2], bh[3]);
                MMA16816(c2, al[1], bh[0], bh[1]);
                MMA16816(c3, al[1], bh[2], bh[3]);
            }
        }
    }
    __syncthreads();

    float* stage = (float*)smraw;
    int g = lane >> 2, i2 = (lane & 3) * 2;
    #pragma unroll
    for (int mf = 0; mf < 2; mf++)
        #pragma unroll
        for (int nf = 0; nf < 8; nf++) {
            float* c = &acc[(mf * 8 + nf) * 4];
            int r = wm * 32 + mf * 16 + g;
            int col = wn * 64 + nf * 8 + i2;
            stage[r * STAGE_PITCH + col]     = c[0];
            stage[r * STAGE_PITCH + col + 1] = c[1];
            stage[(r + 8) * STAGE_PITCH + col]     = c[2];
            stage[(r + 8) * STAGE_PITCH + col + 1] = c[3];
        }
    __syncthreads();
    {
        int col = t & 127, eh = t >> 7;
        float bias = b2[nq * 128 + col];
        for (int e = eh; e < nE; e += 2)
            atomicAdd(&g_agg[stgt[e] + nq * 128 + col],
                      stage[e * STAGE_PITCH + col] + bias);
    }
}

// ---------------- layernorm + pooled mean ----------------
__global__ void norm_pool_kernel(const float* __restrict__ pos,
                                 const float* __restrict__ ln_g,
                                 const float* __restrict__ ln_b) {
    int b = blockIdx.y;
    int s_base = blockIdx.x * 32;
    int warp = threadIdx.x >> 5, lane = threadIdx.x & 31;
    float gg[8], be[8], pacc[8];
    #pragma unroll
    for (int i = 0; i < 8; i++) {
        gg[i] = ln_g[i * 32 + lane]; be[i] = ln_b[i * 32 + lane]; pacc[i] = 0.0f;
    }
    for (int r = warp; r < 32; r += 8) {
        int ss = s_base + r;
        const float* ag = &g_agg[((size_t)b * S + ss) * D];
        const float* ps = &pos[(size_t)ss * D];
        float x[8]; float sum = 0.0f;
        #pragma unroll
        for (int i = 0; i < 8; i++) { x[i] = ps[i * 32 + lane] + ag[i * 32 + lane]; sum += x[i]; }
        #pragma unroll
        for (int off = 16; off > 0; off >>= 1) sum += __shfl_xor_sync(0xFFFFFFFFu, sum, off);
        float mu = sum * (1.0f / D); float v = 0.0f;
        #pragma unroll
        for (int i = 0; i < 8; i++) { x[i] -= mu; v += x[i] * x[i]; }
        #pragma unroll
        for (int off = 16; off > 0; off >>= 1) v += __shfl_xor_sync(0xFFFFFFFFu, v, off);
        float inv = rsqrtf(v * (1.0f / D) + 1e-5f);
        #pragma unroll
        for (int i = 0; i < 8; i++) pacc[i] += x[i] * inv * gg[i] + be[i];
    }
    __shared__ float sp[256];
    sp[threadIdx.x] = 0.0f;
    __syncthreads();
    #pragma unroll
    for (int i = 0; i < 8; i++) atomicAdd(&sp[i * 32 + lane], pacc[i]);
    __syncthreads();
    atomicAdd(&g_pooled[b * D + threadIdx.x], sp[threadIdx.x] * (1.0f / S));
}

// ---------------- final small MLP ----------------
__global__ void final_kernel(const float* __restrict__ lw1, const float* __restrict__ lb1,
                             const float* __restrict__ lw2, const float* __restrict__ lb2,
                             float* __restrict__ out) {
    __shared__ float P[B * D];
    __shared__ float Hh[B * DL];
    int t = threadIdx.x;
    for (int i = t; i < B * D; i += 256) P[i] = g_pooled[i];
    __syncthreads();
    float a[B];
    #pragma unroll
    for (int b = 0; b < B; b++) a[b] = lb1[t];
    for (int k = 0; k < D; k++) {
        float wv = lw1[k * DL + t];
        #pragma unroll
        for (int b = 0; b < B; b++) a[b] = fmaf(P[b * D + k], wv, a[b]);
    }
    #pragma unroll
    for (int b = 0; b < B; b++) Hh[b * DL + t] = gelu_e(a[b]);
    __syncthreads();
    #pragma unroll
    for (int b = 0; b < B; b++) a[b] = lb2[t];
    for (int k = 0; k < DL; k++) {
        float wv = lw2[k * DL + t];
        #pragma unroll
        for (int b = 0; b < B; b++) a[b] = fmaf(Hh[b * DL + k], wv, a[b]);
    }
    #pragma unroll
    for (int b = 0; b < B; b++) out[b * DL + t] = a[b];
}

// ---------------- launch ----------------
extern "C" void kernel_launch(void* const* d_in, const int* in_sizes, int n_in,
                              void* d_out, int out_size) {
    const float* pos_emb  = (const float*)d_in[0];
    const float* pred_emb = (const float*)d_in[1];
    const float* role_emb = (const float*)d_in[2];
    const float* w1       = (const float*)d_in[3];
    const float* b1       = (const float*)d_in[4];
    const float* w2       = (const float*)d_in[5];
    const float* b2       = (const float*)d_in[6];
    const float* ln_g     = (const float*)d_in[7];
    const float* ln_b     = (const float*)d_in[8];
    const float* lw1      = (const float*)d_in[9];
    const float* lb1      = (const float*)d_in[10];
    const float* lw2      = (const float*)d_in[11];
    const float* lb2      = (const float*)d_in[12];
    const int* pred_idx   = (const int*)d_in[13];
    const int* a0         = (const int*)d_in[14];
    const int* a1         = (const int*)d_in[15];
    const int* role_idx   = (const int*)d_in[16];
    const int* is_role    = (const int*)d_in[17];
    const int* add_rev    = (const int*)d_in[18];
    const int* mask       = (const int*)d_in[19];
    float* out = (float*)d_out;

    cudaFuncSetAttribute(gemm1_kernel, cudaFuncAttributeMaxDynamicSharedMemorySize, DYN_SMEM);
    cudaFuncSetAttribute(gemm2_kernel, cudaFuncAttributeMaxDynamicSharedMemorySize, DYN_SMEM);

    zero_kernel<<<(B * S * D + 255) / 256, 256>>>();
    compact_kernel<<<(NE + 255) / 256, 256>>>(mask, is_role, add_rev);
    {
        int total = TAB_ROWS * 256 + 512 * 768 + 256 * 512;
        prep_kernel<<<(total + 255) / 256, 256>>>(pos_emb, pred_emb, role_emb, w1, w2);
    }
    gemm1_kernel<<<(MAXIT / 128) * 4, 256, DYN_SMEM>>>(pred_idx, a0, a1, role_idx, is_role, b1);
    gemm2_kernel<<<(MAXIT / 128) * 2, 256, DYN_SMEM>>>(a0, a1, is_role, b2);
    dim3 g(S / 32, B);
    norm_pool_kernel<<<g, 256>>>(pos_emb, ln_g, ln_b);
    final_kernel<<<1, 256>>>(lw1, lb1, lw2, lb2, out);
}

// round 10
// speedup vs baseline: 1.1005x; 1.1005x over previous
#include <cuda_runtime.h>
#include <cuda_bf16.h>
#include <math.h>
#include <stdint.h>

#define D    256
#define DL   256
#define S    2048
#define B    8
#define F    8192
#define NE   (B * F)
#define MAXIT (2 * NE)
#define TAB_PRED 2048
#define TAB_ROLE 3072
#define TAB_ROWS 3138
#define STAGE_PITCH 132
#define MAT_BYTES 8192                      // 128 rows x 64B (k=32 bf16), packed + swizzled
#define STAGE_BYTES (4 * MAT_BYTES)         // X hi/lo + W hi/lo = 32768
#define NSTAGE 3
#define DYN_SMEM (NSTAGE * STAGE_BYTES + 1024)   // 99328; epilogue 67584 fits
#define SWZ(o) ((o) ^ (((o) >> 3) & 0x70))

// ---------------- device scratch ----------------
__device__ float g_agg[B * S * D];
__device__ float g_pooled[B * D];
__device__ int   g_items[MAXIT];
__device__ int   g_count;
__device__ __align__(16) __nv_bfloat16 g_tabh[TAB_ROWS * 256];
__device__ __align__(16) __nv_bfloat16 g_tabl[TAB_ROWS * 256];
__device__ __align__(16) __nv_bfloat16 g_w1th[512 * 768];   // W1^T [n][k]
__device__ __align__(16) __nv_bfloat16 g_w1tl[512 * 768];
__device__ __align__(16) __nv_bfloat16 g_w2th[256 * 512];   // W2^T [n][k]
__device__ __align__(16) __nv_bfloat16 g_w2tl[256 * 512];
__device__ __align__(16) __nv_bfloat16 g_Hh[(size_t)MAXIT * 512];
__device__ __align__(16) __nv_bfloat16 g_Hl[(size_t)MAXIT * 512];

__device__ __forceinline__ uint32_t smem_u32_of(const void* p) {
    uint32_t a;
    asm("{ .reg .u64 t; cvta.to.shared.u64 t, %1; cvt.u32.u64 %0, t; }" : "=r"(a) : "l"(p));
    return a;
}
__device__ __forceinline__ float gelu_e(float x) { return x * normcdff(x); }

#define LDSM4(r0, r1, r2, r3, addr) \
    asm volatile("ldmatrix.sync.aligned.m8n8.x4.shared.b16 {%0,%1,%2,%3}, [%4];" \
        : "=r"(r0), "=r"(r1), "=r"(r2), "=r"(r3) : "r"(addr))

#define MMA16816(c, a, b0, b1) \
    asm volatile("mma.sync.aligned.m16n8k16.row.col.f32.bf16.bf16.f32 " \
        "{%0,%1,%2,%3}, {%4,%5,%6,%7}, {%8,%9}, {%0,%1,%2,%3};" \
        : "+f"((c)[0]), "+f"((c)[1]), "+f"((c)[2]), "+f"((c)[3]) \
        : "r"((a)[0]), "r"((a)[1]), "r"((a)[2]), "r"((a)[3]), "r"(b0), "r"(b1))

#define CP16(dst, src) \
    asm volatile("cp.async.cg.shared.global [%0], [%1], 16;" \
        :: "r"(dst), "l"(__cvta_generic_to_global(src)) : "memory")
#define CP_COMMIT() asm volatile("cp.async.commit_group;" ::: "memory")
#define CP_WAIT1()  asm volatile("cp.async.wait_group 1;" ::: "memory")

// ---------------- zero ----------------
__global__ void zero_kernel() {
    int i = blockIdx.x * blockDim.x + threadIdx.x;
    if (i < B * S * D) g_agg[i] = 0.0f;
    if (i < B * D)     g_pooled[i] = 0.0f;
    if (i == 0)        g_count = 0;
}

// ---------------- compact ----------------
__global__ void compact_kernel(const int* __restrict__ mask, const int* __restrict__ is_role,
                               const int* __restrict__ add_rev) {
    int e = blockIdx.x * blockDim.x + threadIdx.x;
    if (e >= NE) return;
    if (!mask[e]) return;
    bool rev = (!is_role[e]) && add_rev[e];
    int slot = atomicAdd(&g_count, rev ? 2 : 1);
    g_items[slot] = e << 1;
    if (rev) g_items[slot + 1] = (e << 1) | 1;
}

// ---------------- prep: split tables + W^T hi/lo ----------------
__global__ void prep_kernel(const float* __restrict__ pos, const float* __restrict__ pred,
                            const float* __restrict__ role,
                            const float* __restrict__ w1, const float* __restrict__ w2) {
    int tid = blockIdx.x * blockDim.x + threadIdx.x;
    const int NTAB = TAB_ROWS * 256;
    const int NW1 = 512 * 768;
    const int NW2 = 256 * 512;
    if (tid < NTAB) {
        int row = tid >> 8, col = tid & 255;
        float v;
        if (row < TAB_PRED)      v = pos[tid];
        else if (row < TAB_ROLE) v = pred[(row - TAB_PRED) * 256 + col];
        else                     v = role[(row - TAB_ROLE) * 256 + col];
        __nv_bfloat16 h = __float2bfloat16(v);
        g_tabh[tid] = h;
        g_tabl[tid] = __float2bfloat16(v - __bfloat162float(h));
    } else if (tid < NTAB + NW1) {
        int u = tid - NTAB;                    // u = n*768 + k
        int n = u / 768, k = u - n * 768;
        float v = w1[(size_t)k * 512 + n];
        __nv_bfloat16 h = __float2bfloat16(v);
        g_w1th[u] = h;
        g_w1tl[u] = __float2bfloat16(v - __bfloat162float(h));
    } else if (tid < NTAB + NW1 + NW2) {
        int u = tid - NTAB - NW1;              // u = n*512 + k
        int n = u / 512, k = u - n * 512;
        float v = w2[(size_t)k * 256 + n];
        __nv_bfloat16 h = __float2bfloat16(v);
        g_w2th[u] = h;
        g_w2tl[u] = __float2bfloat16(v - __bfloat162float(h));
    }
}

// ---------------- GEMM1: X[128x768] @ W1[768x512] -> gelu -> g_H ----------------
// grid = tiles x 4 n-quarters; 3-stage cp.async, single barrier per chunk, SW128 swizzle
__global__ void __launch_bounds__(256, 2)
gemm1_kernel(const int* __restrict__ pred_idx,
             const int* __restrict__ a0, const int* __restrict__ a1,
             const int* __restrict__ role_idx, const int* __restrict__ is_role,
             const float* __restrict__ b1) {
    extern __shared__ char smraw[];
    __shared__ int ssrc[128][3];

    int t = threadIdx.x;
    int tile = blockIdx.x >> 2, nq = blockIdx.x & 3;
    int count = g_count;
    int base = tile * 128;
    if (base >= count) return;
    int nE = min(128, count - base);

    if (t < 128) {
        int r0 = 0, r1 = TAB_PRED, r2 = 0;
        if (t < nE) {
            int item = g_items[base + t];
            int e = item >> 1, dir = item & 1;
            int i0 = a0[e], i1 = a1[e];
            r1 = TAB_PRED + pred_idx[e];
            if (dir == 0) {
                int rr = is_role[e];
                r0 = i0;
                r2 = rr ? (TAB_ROLE + role_idx[e]) : i1;
            } else { r0 = i1; r2 = i0; }
        }
        ssrc[t][0] = r0; ssrc[t][1] = r1; ssrc[t][2] = r2;
    }

    uint32_t raw = smem_u32_of(smraw);
    uint32_t smu = (raw + 1023u) & ~1023u;   // 1024-align for SW128
    __syncthreads();

    int w = t >> 5, lane = t & 31;
    int wm = w >> 1, wn = w & 1;
    int blk = lane >> 3, brow = lane & 7;

    float acc[64];
    #pragma unroll
    for (int i = 0; i < 64; i++) acc[i] = 0.0f;

    const int KC = 24;  // 768 / 32

    #define G1_FILL(kc_, st_) do { \
        uint32_t sb = smu + (st_) * STAGE_BYTES; \
        int seg_ = (kc_) >> 3; \
        int inner_ = ((kc_) & 7) * 64; \
        _Pragma("unroll") \
        for (int i = t; i < 1024; i += 256) { \
            int half_ = i >> 9, j_ = i & 511, e_ = j_ >> 2, q_ = j_ & 3; \
            const char* src_ = (half_ ? (const char*)g_tabl : (const char*)g_tabh) \
                               + (size_t)ssrc[e_][seg_] * 512 + inner_ + q_ * 16; \
            CP16(sb + half_ * MAT_BYTES + SWZ(e_ * 64 + q_ * 16), src_); \
        } \
        _Pragma("unroll") \
        for (int i = t; i < 1024; i += 256) { \
            int half_ = i >> 9, j_ = i & 511, r_ = j_ >> 2, q_ = j_ & 3; \
            const char* src_ = (half_ ? (const char*)g_w1tl : (const char*)g_w1th) \
                               + (size_t)(nq * 128 + r_) * 1536 + (kc_) * 64 + q_ * 16; \
            CP16(sb + 2 * MAT_BYTES + half_ * MAT_BYTES + SWZ(r_ * 64 + q_ * 16), src_); \
        } \
    } while (0)

    G1_FILL(0, 0); CP_COMMIT();
    G1_FILL(1, 1); CP_COMMIT();

    int st = 0;                 // stage of current chunk
    int stn = 2;                // stage to fill next (kc+2)
    for (int kc = 0; kc < KC; kc++) {
        CP_WAIT1();
        __syncthreads();        // all warps done with MMA(kc-1) => stage stn safe to fill
        if (kc + 2 < KC) G1_FILL(kc + 2, stn);
        CP_COMMIT();

        uint32_t sb = smu + st * STAGE_BYTES;
        uint32_t xh_u = sb, xl_u = sb + MAT_BYTES;
        uint32_t wh_u = sb + 2 * MAT_BYTES, wl_u = sb + 3 * MAT_BYTES;

        #pragma unroll
        for (int kk = 0; kk < 2; kk++) {
            uint32_t ah[2][4], al[2][4];
            #pragma unroll
            for (int mf = 0; mf < 2; mf++) {
                uint32_t off = SWZ((uint32_t)(wm * 32 + mf * 16 + (blk & 1) * 8 + brow) * 64
                                   + kk * 32 + (blk >> 1) * 16);
                LDSM4(ah[mf][0], ah[mf][1], ah[mf][2], ah[mf][3], xh_u + off);
                LDSM4(al[mf][0], al[mf][1], al[mf][2], al[mf][3], xl_u + off);
            }
            #pragma unroll
            for (int nf2 = 0; nf2 < 4; nf2++) {
                uint32_t boff = SWZ((uint32_t)(wn * 64 + nf2 * 16 + (blk >> 1) * 8 + brow) * 64
                                    + kk * 32 + (blk & 1) * 16);
                uint32_t bh[4], bl[4];
                LDSM4(bh[0], bh[1], bh[2], bh[3], wh_u + boff);
                LDSM4(bl[0], bl[1], bl[2], bl[3], wl_u + boff);
                float* c0 = &acc[(nf2 * 2) * 4];
                float* c1 = &acc[(nf2 * 2 + 1) * 4];
                float* c2 = &acc[(8 + nf2 * 2) * 4];
                float* c3 = &acc[(8 + nf2 * 2 + 1) * 4];
                MMA16816(c0, ah[0], bh[0], bh[1]);
                MMA16816(c1, ah[0], bh[2], bh[3]);
                MMA16816(c2, ah[1], bh[0], bh[1]);
                MMA16816(c3, ah[1], bh[2], bh[3]);
                MMA16816(c0, ah[0], bl[0], bl[1]);
                MMA16816(c1, ah[0], bl[2], bl[3]);
                MMA16816(c2, ah[1], bl[0], bl[1]);
                MMA16816(c3, ah[1], bl[2], bl[3]);
                MMA16816(c0, al[0], bh[0], bh[1]);
                MMA16816(c1, al[0], bh[2], bh[3]);
                MMA16816(c2, al[1], bh[0], bh[1]);
                MMA16816(c3, al[1], bh[2], bh[3]);
            }
        }
        st = (st + 1 == NSTAGE) ? 0 : st + 1;
        stn = (stn + 1 == NSTAGE) ? 0 : stn + 1;
    }
    __syncthreads();

    // stage accumulators -> bias+gelu+split -> g_H
    float* stage = (float*)smraw;
    int g = lane >> 2, i2 = (lane & 3) * 2;
    #pragma unroll
    for (int mf = 0; mf < 2; mf++)
        #pragma unroll
        for (int nf = 0; nf < 8; nf++) {
            float* c = &acc[(mf * 8 + nf) * 4];
            int r = wm * 32 + mf * 16 + g;
            int col = wn * 64 + nf * 8 + i2;
            stage[r * STAGE_PITCH + col]     = c[0];
            stage[r * STAGE_PITCH + col + 1] = c[1];
            stage[(r + 8) * STAGE_PITCH + col]     = c[2];
            stage[(r + 8) * STAGE_PITCH + col + 1] = c[3];
        }
    __syncthreads();
    {
        int col = t & 127, eh = t >> 7;
        float bias = b1[nq * 128 + col];
        for (int e = eh; e < nE; e += 2) {
            float x = stage[e * STAGE_PITCH + col] + bias;
            float y = gelu_e(x);
            __nv_bfloat16 h = __float2bfloat16(y);
            size_t o = (size_t)(base + e) * 512 + nq * 128 + col;
            g_Hh[o] = h;
            g_Hl[o] = __float2bfloat16(y - __bfloat162float(h));
        }
    }
}

// ---------------- GEMM2: H[128x512] @ W2[512x256] -> +b2 -> atomic scatter ----------------
__global__ void __launch_bounds__(256, 2)
gemm2_kernel(const int* __restrict__ a0, const int* __restrict__ a1,
             const int* __restrict__ is_role, const float* __restrict__ b2) {
    extern __shared__ char smraw[];
    __shared__ int stgt[128];

    int t = threadIdx.x;
    int tile = blockIdx.x >> 1, nq = blockIdx.x & 1;
    int count = g_count;
    int base = tile * 128;
    if (base >= count) return;
    int nE = min(128, count - base);

    if (t < 128) {
        int tg = 0, bidx = 0;
        if (t < nE) {
            int item = g_items[base + t];
            int e = item >> 1, dir = item & 1;
            bidx = e >> 13;
            int i0 = a0[e], i1 = a1[e];
            if (dir == 0) { int rr = is_role[e]; tg = rr ? i0 : i1; }
            else tg = i0;
        }
        stgt[t] = (bidx * S + tg) * D;
    }

    uint32_t raw = smem_u32_of(smraw);
    uint32_t smu = (raw + 1023u) & ~1023u;
    __syncthreads();

    int w = t >> 5, lane = t & 31;
    int wm = w >> 1, wn = w & 1;
    int blk = lane >> 3, brow = lane & 7;

    float acc[64];
    #pragma unroll
    for (int i = 0; i < 64; i++) acc[i] = 0.0f;

    const int KC = 16;  // 512 / 32

    #define G2_FILL(kc_, st_) do { \
        uint32_t sb = smu + (st_) * STAGE_BYTES; \
        _Pragma("unroll") \
        for (int i = t; i < 1024; i += 256) { \
            int half_ = i >> 9, j_ = i & 511, e_ = j_ >> 2, q_ = j_ & 3; \
            const char* src_ = (half_ ? (const char*)g_Hl : (const char*)g_Hh) \
                               + (size_t)(base + e_) * 1024 + (kc_) * 64 + q_ * 16; \
            CP16(sb + half_ * MAT_BYTES + SWZ(e_ * 64 + q_ * 16), src_); \
        } \
        _Pragma("unroll") \
        for (int i = t; i < 1024; i += 256) { \
            int half_ = i >> 9, j_ = i & 511, r_ = j_ >> 2, q_ = j_ & 3; \
            const char* src_ = (half_ ? (const char*)g_w2tl : (const char*)g_w2th) \
                               + (size_t)(nq * 128 + r_) * 1024 + (kc_) * 64 + q_ * 16; \
            CP16(sb + 2 * MAT_BYTES + half_ * MAT_BYTES + SWZ(r_ * 64 + q_ * 16), src_); \
        } \
    } while (0)

    G2_FILL(0, 0); CP_COMMIT();
    G2_FILL(1, 1); CP_COMMIT();

    int st = 0, stn = 2;
    for (int kc = 0; kc < KC; kc++) {
        CP_WAIT1();
        __syncthreads();
        if (kc + 2 < KC) G2_FILL(kc + 2, stn);
        CP_COMMIT();

        uint32_t sb = smu + st * STAGE_BYTES;
        uint32_t xh_u = sb, xl_u = sb + MAT_BYTES;
        uint32_t wh_u = sb + 2 * MAT_BYTES, wl_u = sb + 3 * MAT_BYTES;

        #pragma unroll
        for (int kk = 0; kk < 2; kk++) {
            uint32_t ah[2][4], al[2][4];
            #pragma unroll
            for (int mf = 0; mf < 2; mf++) {
                uint32_t off = SWZ((uint32_t)(wm * 32 + mf * 16 + (blk & 1) * 8 + brow) * 64
                                   + kk * 32 + (blk >> 1) * 16);
                LDSM4(ah[mf][0], ah[mf][1], ah[mf][2], ah[mf][3], xh_u + off);
                LDSM4(al[mf][0], al[mf][1], al[mf][2], al[mf][3], xl_u + off);
            }
            #pragma unroll
            for (int nf2 = 0; nf2 < 4; nf2++) {
                uint32_t boff = SWZ((uint32_t)(wn * 64 + nf2 * 16 + (blk >> 1) * 8 + brow) * 64
                                    + kk * 32 + (blk & 1) * 16);
                uint32_t bh[4], bl[4];
                LDSM4(bh[0], bh[1], bh[2], bh[3], wh_u + boff);
                LDSM4(bl[0], bl[1], bl[2], bl[3], wl_u + boff);
                float* c0 = &acc[(nf2 * 2) * 4];
                float* c1 = &acc[(nf2 * 2 + 1) * 4];
                float* c2 = &acc[(8 + nf2 * 2) * 4];
                float* c3 = &acc[(8 + nf2 * 2 + 1) * 4];
                MMA16816(c0, ah[0], bh[0], bh[1]);
                MMA16816(c1, ah[0], bh[2], bh[3]);
                MMA16816(c2, ah[1], bh[0], bh[1]);
                MMA16816(c3, ah[1], bh[2], bh[3]);
                MMA16816(c0, ah[0], bl[0], bl[1]);
                MMA16816(c1, ah[0], bl[2], bl[3]);
                MMA16816(c2, ah[1], bl[0], bl[1]);
                MMA16816(c3, ah[1], bl[2], bl[3]);
                MMA16816(c0, al[0], bh[0], bh[1]);
                MMA16816(c1, al[0], bh[2], bh[3]);
                MMA16816(c2, al[1], bh[0], bh[1]);
                MMA16816(c3, al[1], bh[2], bh[3]);
            }
        }
        st = (st + 1 == NSTAGE) ? 0 : st + 1;
        stn = (stn + 1 == NSTAGE) ? 0 : stn + 1;
    }
    __syncthreads();

    float* stage = (float*)smraw;
    int g = lane >> 2, i2 = (lane & 3) * 2;
    #pragma unroll
    for (int mf = 0; mf < 2; mf++)
        #pragma unroll
        for (int nf = 0; nf < 8; nf++) {
            float* c = &acc[(mf * 8 + nf) * 4];
            int r = wm * 32 + mf * 16 + g;
            int col = wn * 64 + nf * 8 + i2;
            stage[r * STAGE_PITCH + col]     = c[0];
            stage[r * STAGE_PITCH + col + 1] = c[1];
            stage[(r + 8) * STAGE_PITCH + col]     = c[2];
            stage[(r + 8) * STAGE_PITCH + col + 1] = c[3];
        }
    __syncthreads();
    {
        int col = t & 127, eh = t >> 7;
        float bias = b2[nq * 128 + col];
        for (int e = eh; e < nE; e += 2)
            atomicAdd(&g_agg[stgt[e] + nq * 128 + col],
                      stage[e * STAGE_PITCH + col] + bias);
    }
}

// ---------------- layernorm + pooled mean ----------------
__global__ void norm_pool_kernel(const float* __restrict__ pos,
                                 const float* __restrict__ ln_g,
                                 const float* __restrict__ ln_b) {
    int b = blockIdx.y;
    int s_base = blockIdx.x * 32;
    int warp = threadIdx.x >> 5, lane = threadIdx.x & 31;
    float gg[8], be[8], pacc[8];
    #pragma unroll
    for (int i = 0; i < 8; i++) {
        gg[i] = ln_g[i * 32 + lane]; be[i] = ln_b[i * 32 + lane]; pacc[i] = 0.0f;
    }
    for (int r = warp; r < 32; r += 8) {
        int ss = s_base + r;
        const float* ag = &g_agg[((size_t)b * S + ss) * D];
        const float* ps = &pos[(size_t)ss * D];
        float x[8]; float sum = 0.0f;
        #pragma unroll
        for (int i = 0; i < 8; i++) { x[i] = ps[i * 32 + lane] + ag[i * 32 + lane]; sum += x[i]; }
        #pragma unroll
        for (int off = 16; off > 0; off >>= 1) sum += __shfl_xor_sync(0xFFFFFFFFu, sum, off);
        float mu = sum * (1.0f / D); float v = 0.0f;
        #pragma unroll
        for (int i = 0; i < 8; i++) { x[i] -= mu; v += x[i] * x[i]; }
        #pragma unroll
        for (int off = 16; off > 0; off >>= 1) v += __shfl_xor_sync(0xFFFFFFFFu, v, off);
        float inv = rsqrtf(v * (1.0f / D) + 1e-5f);
        #pragma unroll
        for (int i = 0; i < 8; i++) pacc[i] += x[i] * inv * gg[i] + be[i];
    }
    __shared__ float sp[256];
    sp[threadIdx.x] = 0.0f;
    __syncthreads();
    #pragma unroll
    for (int i = 0; i < 8; i++) atomicAdd(&sp[i * 32 + lane], pacc[i]);
    __syncthreads();
    atomicAdd(&g_pooled[b * D + threadIdx.x], sp[threadIdx.x] * (1.0f / S));
}

// ---------------- final small MLP ----------------
__global__ void final_kernel(const float* __restrict__ lw1, const float* __restrict__ lb1,
                             const float* __restrict__ lw2, const float* __restrict__ lb2,
                             float* __restrict__ out) {
    __shared__ float P[B * D];
    __shared__ float Hh[B * DL];
    int t = threadIdx.x;
    for (int i = t; i < B * D; i += 256) P[i] = g_pooled[i];
    __syncthreads();
    float a[B];
    #pragma unroll
    for (int b = 0; b < B; b++) a[b] = lb1[t];
    for (int k = 0; k < D; k++) {
        float wv = lw1[k * DL + t];
        #pragma unroll
        for (int b = 0; b < B; b++) a[b] = fmaf(P[b * D + k], wv, a[b]);
    }
    #pragma unroll
    for (int b = 0; b < B; b++) Hh[b * DL + t] = gelu_e(a[b]);
    __syncthreads();
    #pragma unroll
    for (int b = 0; b < B; b++) a[b] = lb2[t];
    for (int k = 0; k < DL; k++) {
        float wv = lw2[k * DL + t];
        #pragma unroll
        for (int b = 0; b < B; b++) a[b] = fmaf(Hh[b * DL + k], wv, a[b]);
    }
    #pragma unroll
    for (int b = 0; b < B; b++) out[b * DL + t] = a[b];
}

// ---------------- launch ----------------
extern "C" void kernel_launch(void* const* d_in, const int* in_sizes, int n_in,
                              void* d_out, int out_size) {
    const float* pos_emb  = (const float*)d_in[0];
    const float* pred_emb = (const float*)d_in[1];
    const float* role_emb = (const float*)d_in[2];
    const float* w1       = (const float*)d_in[3];
    const float* b1       = (const float*)d_in[4];
    const float* w2       = (const float*)d_in[5];
    const float* b2       = (const float*)d_in[6];
    const float* ln_g     = (const float*)d_in[7];
    const float* ln_b     = (const float*)d_in[8];
    const float* lw1      = (const float*)d_in[9];
    const float* lb1      = (const float*)d_in[10];
    const float* lw2      = (const float*)d_in[11];
    const float* lb2      = (const float*)d_in[12];
    const int* pred_idx   = (const int*)d_in[13];
    const int* a0         = (const int*)d_in[14];
    const int* a1         = (const int*)d_in[15];
    const int* role_idx   = (const int*)d_in[16];
    const int* is_role    = (const int*)d_in[17];
    const int* add_rev    = (const int*)d_in[18];
    const int* mask       = (const int*)d_in[19];
    float* out = (float*)d_out;

    cudaFuncSetAttribute(gemm1_kernel, cudaFuncAttributeMaxDynamicSharedMemorySize, DYN_SMEM);
    cudaFuncSetAttribute(gemm2_kernel, cudaFuncAttributeMaxDynamicSharedMemorySize, DYN_SMEM);

    zero_kernel<<<(B * S * D + 255) / 256, 256>>>();
    compact_kernel<<<(NE + 255) / 256, 256>>>(mask, is_role, add_rev);
    {
        int total = TAB_ROWS * 256 + 512 * 768 + 256 * 512;
        prep_kernel<<<(total + 255) / 256, 256>>>(pos_emb, pred_emb, role_emb, w1, w2);
    }
    gemm1_kernel<<<(MAXIT / 128) * 4, 256, DYN_SMEM>>>(pred_idx, a0, a1, role_idx, is_role, b1);
    gemm2_kernel<<<(MAXIT / 128) * 2, 256, DYN_SMEM>>>(a0, a1, is_role, b2);
    dim3 g(S / 32, B);
    norm_pool_kernel<<<g, 256>>>(pos_emb, ln_g, ln_b);
    final_kernel<<<1, 256>>>(lw1, lb1, lw2, lb2, out);
}

// round 11
// speedup vs baseline: 1.4847x; 1.3492x over previous
#include <cuda_runtime.h>
#include <cuda_fp16.h>
#include <math.h>
#include <stdint.h>

#define D    256
#define DL   256
#define S    2048
#define B    8
#define F    8192
#define NE   (B * F)
#define MAXIT (2 * NE)
#define TAB_PRED 2048
#define TAB_ROLE 3072
#define TAB_ROWS 3138
#define STAGE_PITCH 132
#define MAT_BYTES 8192                      // 128 rows x 64B (k=32 fp16), packed + swizzled
#define STAGE_BYTES (3 * MAT_BYTES)         // X + Wh + Wl = 24576
#define NSTAGE 4
#define DYN_SMEM (NSTAGE * STAGE_BYTES + 1024)   // 99328; epilogue 67584 fits
#define SWZ(o) ((o) ^ (((o) >> 3) & 0x70))

// ---------------- device scratch ----------------
__device__ float g_agg[B * S * D];
__device__ float g_pooled[B * D];
__device__ int   g_items[MAXIT];
__device__ int   g_count;
__device__ __align__(16) __half g_tab[TAB_ROWS * 256];
__device__ __align__(16) __half g_w1th[512 * 768];   // W1^T [n][k] hi
__device__ __align__(16) __half g_w1tl[512 * 768];   // W1^T lo
__device__ __align__(16) __half g_w2th[256 * 512];   // W2^T hi
__device__ __align__(16) __half g_w2tl[256 * 512];   // W2^T lo
__device__ __align__(16) __half g_H[(size_t)MAXIT * 512];

__device__ __forceinline__ uint32_t smem_u32_of(const void* p) {
    uint32_t a;
    asm("{ .reg .u64 t; cvta.to.shared.u64 t, %1; cvt.u32.u64 %0, t; }" : "=r"(a) : "l"(p));
    return a;
}
__device__ __forceinline__ float gelu_e(float x) { return x * normcdff(x); }

#define LDSM4(r0, r1, r2, r3, addr) \
    asm volatile("ldmatrix.sync.aligned.m8n8.x4.shared.b16 {%0,%1,%2,%3}, [%4];" \
        : "=r"(r0), "=r"(r1), "=r"(r2), "=r"(r3) : "r"(addr))

#define MMA16816(c, a, b0, b1) \
    asm volatile("mma.sync.aligned.m16n8k16.row.col.f32.f16.f16.f32 " \
        "{%0,%1,%2,%3}, {%4,%5,%6,%7}, {%8,%9}, {%0,%1,%2,%3};" \
        : "+f"((c)[0]), "+f"((c)[1]), "+f"((c)[2]), "+f"((c)[3]) \
        : "r"((a)[0]), "r"((a)[1]), "r"((a)[2]), "r"((a)[3]), "r"(b0), "r"(b1))

#define CP16(dst, src) \
    asm volatile("cp.async.cg.shared.global [%0], [%1], 16;" \
        :: "r"(dst), "l"(__cvta_generic_to_global(src)) : "memory")
#define CP_COMMIT() asm volatile("cp.async.commit_group;" ::: "memory")
#define CP_WAIT2()  asm volatile("cp.async.wait_group 2;" ::: "memory")

// ---------------- zero ----------------
__global__ void zero_kernel() {
    int i = blockIdx.x * blockDim.x + threadIdx.x;
    if (i < B * S * D) g_agg[i] = 0.0f;
    if (i < B * D)     g_pooled[i] = 0.0f;
    if (i == 0)        g_count = 0;
}

// ---------------- compact ----------------
__global__ void compact_kernel(const int* __restrict__ mask, const int* __restrict__ is_role,
                               const int* __restrict__ add_rev) {
    int e = blockIdx.x * blockDim.x + threadIdx.x;
    if (e >= NE) return;
    if (!mask[e]) return;
    bool rev = (!is_role[e]) && add_rev[e];
    int slot = atomicAdd(&g_count, rev ? 2 : 1);
    g_items[slot] = e << 1;
    if (rev) g_items[slot + 1] = (e << 1) | 1;
}

// ---------------- prep: fp16 table + split W^T hi/lo ----------------
__global__ void prep_kernel(const float* __restrict__ pos, const float* __restrict__ pred,
                            const float* __restrict__ role,
                            const float* __restrict__ w1, const float* __restrict__ w2) {
    int tid = blockIdx.x * blockDim.x + threadIdx.x;
    const int NTAB = TAB_ROWS * 256;
    const int NW1 = 512 * 768;
    const int NW2 = 256 * 512;
    if (tid < NTAB) {
        int row = tid >> 8, col = tid & 255;
        float v;
        if (row < TAB_PRED)      v = pos[tid];
        else if (row < TAB_ROLE) v = pred[(row - TAB_PRED) * 256 + col];
        else                     v = role[(row - TAB_ROLE) * 256 + col];
        g_tab[tid] = __float2half(v);
    } else if (tid < NTAB + NW1) {
        int u = tid - NTAB;                    // u = n*768 + k
        int n = u / 768, k = u - n * 768;
        float v = w1[(size_t)k * 512 + n];
        __half h = __float2half(v);
        g_w1th[u] = h;
        g_w1tl[u] = __float2half(v - __half2float(h));
    } else if (tid < NTAB + NW1 + NW2) {
        int u = tid - NTAB - NW1;              // u = n*512 + k
        int n = u / 512, k = u - n * 512;
        float v = w2[(size_t)k * 256 + n];
        __half h = __float2half(v);
        g_w2th[u] = h;
        g_w2tl[u] = __float2half(v - __half2float(h));
    }
}

// ---------------- GEMM1: X[128x768] @ W1[768x512] -> gelu -> g_H ----------------
// grid = tiles x 4 n-quarters; 4-stage cp.async, 2-pass fp16 split
__global__ void __launch_bounds__(256, 2)
gemm1_kernel(const int* __restrict__ pred_idx,
             const int* __restrict__ a0, const int* __restrict__ a1,
             const int* __restrict__ role_idx, const int* __restrict__ is_role,
             const float* __restrict__ b1) {
    extern __shared__ char smraw[];
    __shared__ int ssrc[128][3];

    int t = threadIdx.x;
    int tile = blockIdx.x >> 2, nq = blockIdx.x & 3;
    int count = g_count;
    int base = tile * 128;
    if (base >= count) return;
    int nE = min(128, count - base);

    if (t < 128) {
        int r0 = 0, r1 = TAB_PRED, r2 = 0;
        if (t < nE) {
            int item = g_items[base + t];
            int e = item >> 1, dir = item & 1;
            int i0 = a0[e], i1 = a1[e];
            r1 = TAB_PRED + pred_idx[e];
            if (dir == 0) {
                int rr = is_role[e];
                r0 = i0;
                r2 = rr ? (TAB_ROLE + role_idx[e]) : i1;
            } else { r0 = i1; r2 = i0; }
        }
        ssrc[t][0] = r0; ssrc[t][1] = r1; ssrc[t][2] = r2;
    }

    uint32_t raw = smem_u32_of(smraw);
    uint32_t smu = (raw + 1023u) & ~1023u;
    __syncthreads();

    int w = t >> 5, lane = t & 31;
    int wm = w >> 1, wn = w & 1;
    int blk = lane >> 3, brow = lane & 7;

    float acc[64];
    #pragma unroll
    for (int i = 0; i < 64; i++) acc[i] = 0.0f;

    const int KC = 24;  // 768 / 32

    // fill: X chunk (512 cp), W hi+lo (1024 cp)
    #define G1_FILL(kc_, st_) do { \
        uint32_t sb = smu + (st_) * STAGE_BYTES; \
        int seg_ = (kc_) >> 3; \
        int innb_ = ((kc_) & 7) * 64; \
        _Pragma("unroll") \
        for (int i = t; i < 512; i += 256) { \
            int e_ = i >> 2, q_ = i & 3; \
            const char* src_ = (const char*)g_tab \
                               + (size_t)ssrc[e_][seg_] * 512 + innb_ + q_ * 16; \
            CP16(sb + SWZ(e_ * 64 + q_ * 16), src_); \
        } \
        _Pragma("unroll") \
        for (int i = t; i < 1024; i += 256) { \
            int half_ = i >> 9, j_ = i & 511, r_ = j_ >> 2, q_ = j_ & 3; \
            const char* src_ = (half_ ? (const char*)g_w1tl : (const char*)g_w1th) \
                               + (size_t)(nq * 128 + r_) * 1536 + (kc_) * 64 + q_ * 16; \
            CP16(sb + MAT_BYTES + half_ * MAT_BYTES + SWZ(r_ * 64 + q_ * 16), src_); \
        } \
    } while (0)

    G1_FILL(0, 0); CP_COMMIT();
    G1_FILL(1, 1); CP_COMMIT();
    G1_FILL(2, 2); CP_COMMIT();

    int st = 0;                 // stage of current chunk
    int stn = 3;                // stage to fill next (kc+3)
    for (int kc = 0; kc < KC; kc++) {
        CP_WAIT2();
        __syncthreads();        // all warps done with MMA(kc-1) => stage stn safe
        if (kc + 3 < KC) G1_FILL(kc + 3, stn);
        CP_COMMIT();

        uint32_t sb = smu + st * STAGE_BYTES;
        uint32_t xh_u = sb;
        uint32_t wh_u = sb + MAT_BYTES, wl_u = sb + 2 * MAT_BYTES;

        #pragma unroll
        for (int kk = 0; kk < 2; kk++) {
            uint32_t ah[2][4];
            #pragma unroll
            for (int mf = 0; mf < 2; mf++) {
                uint32_t off = SWZ((uint32_t)(wm * 32 + mf * 16 + (blk & 1) * 8 + brow) * 64
                                   + kk * 32 + (blk >> 1) * 16);
                LDSM4(ah[mf][0], ah[mf][1], ah[mf][2], ah[mf][3], xh_u + off);
            }
            #pragma unroll
            for (int nf2 = 0; nf2 < 4; nf2++) {
                uint32_t boff = SWZ((uint32_t)(wn * 64 + nf2 * 16 + (blk >> 1) * 8 + brow) * 64
                                    + kk * 32 + (blk & 1) * 16);
                uint32_t bh[4], bl[4];
                LDSM4(bh[0], bh[1], bh[2], bh[3], wh_u + boff);
                LDSM4(bl[0], bl[1], bl[2], bl[3], wl_u + boff);
                float* c0 = &acc[(nf2 * 2) * 4];
                float* c1 = &acc[(nf2 * 2 + 1) * 4];
                float* c2 = &acc[(8 + nf2 * 2) * 4];
                float* c3 = &acc[(8 + nf2 * 2 + 1) * 4];
                MMA16816(c0, ah[0], bh[0], bh[1]);
                MMA16816(c1, ah[0], bh[2], bh[3]);
                MMA16816(c2, ah[1], bh[0], bh[1]);
                MMA16816(c3, ah[1], bh[2], bh[3]);
                MMA16816(c0, ah[0], bl[0], bl[1]);
                MMA16816(c1, ah[0], bl[2], bl[3]);
                MMA16816(c2, ah[1], bl[0], bl[1]);
                MMA16816(c3, ah[1], bl[2], bl[3]);
            }
        }
        st = (st + 1 == NSTAGE) ? 0 : st + 1;
        stn = (stn + 1 == NSTAGE) ? 0 : stn + 1;
    }
    __syncthreads();

    // stage accumulators -> bias+gelu -> g_H (fp16)
    float* stage = (float*)smraw;
    int g = lane >> 2, i2 = (lane & 3) * 2;
    #pragma unroll
    for (int mf = 0; mf < 2; mf++)
        #pragma unroll
        for (int nf = 0; nf < 8; nf++) {
            float* c = &acc[(mf * 8 + nf) * 4];
            int r = wm * 32 + mf * 16 + g;
            int col = wn * 64 + nf * 8 + i2;
            stage[r * STAGE_PITCH + col]     = c[0];
            stage[r * STAGE_PITCH + col + 1] = c[1];
            stage[(r + 8) * STAGE_PITCH + col]     = c[2];
            stage[(r + 8) * STAGE_PITCH + col + 1] = c[3];
        }
    __syncthreads();
    {
        int col = t & 127, eh = t >> 7;
        float bias = b1[nq * 128 + col];
        for (int e = eh; e < nE; e += 2) {
            float x = stage[e * STAGE_PITCH + col] + bias;
            g_H[(size_t)(base + e) * 512 + nq * 128 + col] = __float2half(gelu_e(x));
        }
    }
}

// ---------------- GEMM2: H[128x512] @ W2[512x256] -> +b2 -> atomic scatter ----------------
__global__ void __launch_bounds__(256, 2)
gemm2_kernel(const int* __restrict__ a0, const int* __restrict__ a1,
             const int* __restrict__ is_role, const float* __restrict__ b2) {
    extern __shared__ char smraw[];
    __shared__ int stgt[128];

    int t = threadIdx.x;
    int tile = blockIdx.x >> 1, nq = blockIdx.x & 1;
    int count = g_count;
    int base = tile * 128;
    if (base >= count) return;
    int nE = min(128, count - base);

    if (t < 128) {
        int tg = 0, bidx = 0;
        if (t < nE) {
            int item = g_items[base + t];
            int e = item >> 1, dir = item & 1;
            bidx = e >> 13;
            int i0 = a0[e], i1 = a1[e];
            if (dir == 0) { int rr = is_role[e]; tg = rr ? i0 : i1; }
            else tg = i0;
        }
        stgt[t] = (bidx * S + tg) * D;
    }

    uint32_t raw = smem_u32_of(smraw);
    uint32_t smu = (raw + 1023u) & ~1023u;
    __syncthreads();

    int w = t >> 5, lane = t & 31;
    int wm = w >> 1, wn = w & 1;
    int blk = lane >> 3, brow = lane & 7;

    float acc[64];
    #pragma unroll
    for (int i = 0; i < 64; i++) acc[i] = 0.0f;

    const int KC = 16;  // 512 / 32

    #define G2_FILL(kc_, st_) do { \
        uint32_t sb = smu + (st_) * STAGE_BYTES; \
        _Pragma("unroll") \
        for (int i = t; i < 512; i += 256) { \
            int e_ = i >> 2, q_ = i & 3; \
            const char* src_ = (const char*)g_H \
                               + (size_t)(base + e_) * 1024 + (kc_) * 64 + q_ * 16; \
            CP16(sb + SWZ(e_ * 64 + q_ * 16), src_); \
        } \
        _Pragma("unroll") \
        for (int i = t; i < 1024; i += 256) { \
            int half_ = i >> 9, j_ = i & 511, r_ = j_ >> 2, q_ = j_ & 3; \
            const char* src_ = (half_ ? (const char*)g_w2tl : (const char*)g_w2th) \
                               + (size_t)(nq * 128 + r_) * 1024 + (kc_) * 64 + q_ * 16; \
            CP16(sb + MAT_BYTES + half_ * MAT_BYTES + SWZ(r_ * 64 + q_ * 16), src_); \
        } \
    } while (0)

    G2_FILL(0, 0); CP_COMMIT();
    G2_FILL(1, 1); CP_COMMIT();
    G2_FILL(2, 2); CP_COMMIT();

    int st = 0, stn = 3;
    for (int kc = 0; kc < KC; kc++) {
        CP_WAIT2();
        __syncthreads();
        if (kc + 3 < KC) G2_FILL(kc + 3, stn);
        CP_COMMIT();

        uint32_t sb = smu + st * STAGE_BYTES;
        uint32_t xh_u = sb;
        uint32_t wh_u = sb + MAT_BYTES, wl_u = sb + 2 * MAT_BYTES;

        #pragma unroll
        for (int kk = 0; kk < 2; kk++) {
            uint32_t ah[2][4];
            #pragma unroll
            for (int mf = 0; mf < 2; mf++) {
                uint32_t off = SWZ((uint32_t)(wm * 32 + mf * 16 + (blk & 1) * 8 + brow) * 64
                                   + kk * 32 + (blk >> 1) * 16);
                LDSM4(ah[mf][0], ah[mf][1], ah[mf][2], ah[mf][3], xh_u + off);
            }
            #pragma unroll
            for (int nf2 = 0; nf2 < 4; nf2++) {
                uint32_t boff = SWZ((uint32_t)(wn * 64 + nf2 * 16 + (blk >> 1) * 8 + brow) * 64
                                    + kk * 32 + (blk & 1) * 16);
                uint32_t bh[4], bl[4];
                LDSM4(bh[0], bh[1], bh[2], bh[3], wh_u + boff);
                LDSM4(bl[0], bl[1], bl[2], bl[3], wl_u + boff);
                float* c0 = &acc[(nf2 * 2) * 4];
                float* c1 = &acc[(nf2 * 2 + 1) * 4];
                float* c2 = &acc[(8 + nf2 * 2) * 4];
                float* c3 = &acc[(8 + nf2 * 2 + 1) * 4];
                MMA16816(c0, ah[0], bh[0], bh[1]);
                MMA16816(c1, ah[0], bh[2], bh[3]);
                MMA16816(c2, ah[1], bh[0], bh[1]);
                MMA16816(c3, ah[1], bh[2], bh[3]);
                MMA16816(c0, ah[0], bl[0], bl[1]);
                MMA16816(c1, ah[0], bl[2], bl[3]);
                MMA16816(c2, ah[1], bl[0], bl[1]);
                MMA16816(c3, ah[1], bl[2], bl[3]);
            }
        }
        st = (st + 1 == NSTAGE) ? 0 : st + 1;
        stn = (stn + 1 == NSTAGE) ? 0 : stn + 1;
    }
    __syncthreads();

    float* stage = (float*)smraw;
    int g = lane >> 2, i2 = (lane & 3) * 2;
    #pragma unroll
    for (int mf = 0; mf < 2; mf++)
        #pragma unroll
        for (int nf = 0; nf < 8; nf++) {
            float* c = &acc[(mf * 8 + nf) * 4];
            int r = wm * 32 + mf * 16 + g;
            int col = wn * 64 + nf * 8 + i2;
            stage[r * STAGE_PITCH + col]     = c[0];
            stage[r * STAGE_PITCH + col + 1] = c[1];
            stage[(r + 8) * STAGE_PITCH + col]     = c[2];
            stage[(r + 8) * STAGE_PITCH + col + 1] = c[3];
        }
    __syncthreads();
    {
        int col = t & 127, eh = t >> 7;
        float bias = b2[nq * 128 + col];
        for (int e = eh; e < nE; e += 2)
            atomicAdd(&g_agg[stgt[e] + nq * 128 + col],
                      stage[e * STAGE_PITCH + col] + bias);
    }
}

// ---------------- layernorm + pooled mean ----------------
__global__ void norm_pool_kernel(const float* __restrict__ pos,
                                 const float* __restrict__ ln_g,
                                 const float* __restrict__ ln_b) {
    int b = blockIdx.y;
    int s_base = blockIdx.x * 32;
    int warp = threadIdx.x >> 5, lane = threadIdx.x & 31;
    float gg[8], be[8], pacc[8];
    #pragma unroll
    for (int i = 0; i < 8; i++) {
        gg[i] = ln_g[i * 32 + lane]; be[i] = ln_b[i * 32 + lane]; pacc[i] = 0.0f;
    }
    for (int r = warp; r < 32; r += 8) {
        int ss = s_base + r;
        const float* ag = &g_agg[((size_t)b * S + ss) * D];
        const float* ps = &pos[(size_t)ss * D];
        float x[8]; float sum = 0.0f;
        #pragma unroll
        for (int i = 0; i < 8; i++) { x[i] = ps[i * 32 + lane] + ag[i * 32 + lane]; sum += x[i]; }
        #pragma unroll
        for (int off = 16; off > 0; off >>= 1) sum += __shfl_xor_sync(0xFFFFFFFFu, sum, off);
        float mu = sum * (1.0f / D); float v = 0.0f;
        #pragma unroll
        for (int i = 0; i < 8; i++) { x[i] -= mu; v += x[i] * x[i]; }
        #pragma unroll
        for (int off = 16; off > 0; off >>= 1) v += __shfl_xor_sync(0xFFFFFFFFu, v, off);
        float inv = rsqrtf(v * (1.0f / D) + 1e-5f);
        #pragma unroll
        for (int i = 0; i < 8; i++) pacc[i] += x[i] * inv * gg[i] + be[i];
    }
    __shared__ float sp[256];
    sp[threadIdx.x] = 0.0f;
    __syncthreads();
    #pragma unroll
    for (int i = 0; i < 8; i++) atomicAdd(&sp[i * 32 + lane], pacc[i]);
    __syncthreads();
    atomicAdd(&g_pooled[b * D + threadIdx.x], sp[threadIdx.x] * (1.0f / S));
}

// ---------------- final small MLP ----------------
__global__ void final_kernel(const float* __restrict__ lw1, const float* __restrict__ lb1,
                             const float* __restrict__ lw2, const float* __restrict__ lb2,
                             float* __restrict__ out) {
    __shared__ float P[B * D];
    __shared__ float Hh[B * DL];
    int t = threadIdx.x;
    for (int i = t; i < B * D; i += 256) P[i] = g_pooled[i];
    __syncthreads();
    float a[B];
    #pragma unroll
    for (int b = 0; b < B; b++) a[b] = lb1[t];
    for (int k = 0; k < D; k++) {
        float wv = lw1[k * DL + t];
        #pragma unroll
        for (int b = 0; b < B; b++) a[b] = fmaf(P[b * D + k], wv, a[b]);
    }
    #pragma unroll
    for (int b = 0; b < B; b++) Hh[b * DL + t] = gelu_e(a[b]);
    __syncthreads();
    #pragma unroll
    for (int b = 0; b < B; b++) a[b] = lb2[t];
    for (int k = 0; k < DL; k++) {
        float wv = lw2[k * DL + t];
        #pragma unroll
        for (int b = 0; b < B; b++) a[b] = fmaf(Hh[b * DL + k], wv, a[b]);
    }
    #pragma unroll
    for (int b = 0; b < B; b++) out[b * DL + t] = a[b];
}

// ---------------- launch ----------------
extern "C" void kernel_launch(void* const* d_in, const int* in_sizes, int n_in,
                              void* d_out, int out_size) {
    const float* pos_emb  = (const float*)d_in[0];
    const float* pred_emb = (const float*)d_in[1];
    const float* role_emb = (const float*)d_in[2];
    const float* w1       = (const float*)d_in[3];
    const float* b1       = (const float*)d_in[4];
    const float* w2       = (const float*)d_in[5];
    const float* b2       = (const float*)d_in[6];
    const float* ln_g     = (const float*)d_in[7];
    const float* ln_b     = (const float*)d_in[8];
    const float* lw1      = (const float*)d_in[9];
    const float* lb1      = (const float*)d_in[10];
    const float* lw2      = (const float*)d_in[11];
    const float* lb2      = (const float*)d_in[12];
    const int* pred_idx   = (const int*)d_in[13];
    const int* a0         = (const int*)d_in[14];
    const int* a1         = (const int*)d_in[15];
    const int* role_idx   = (const int*)d_in[16];
    const int* is_role    = (const int*)d_in[17];
    const int* add_rev    = (const int*)d_in[18];
    const int* mask       = (const int*)d_in[19];
    float* out = (float*)d_out;

    cudaFuncSetAttribute(gemm1_kernel, cudaFuncAttributeMaxDynamicSharedMemorySize, DYN_SMEM);
    cudaFuncSetAttribute(gemm2_kernel, cudaFuncAttributeMaxDynamicSharedMemorySize, DYN_SMEM);

    zero_kernel<<<(B * S * D + 255) / 256, 256>>>();
    compact_kernel<<<(NE + 255) / 256, 256>>>(mask, is_role, add_rev);
    {
        int total = TAB_ROWS * 256 + 512 * 768 + 256 * 512;
        prep_kernel<<<(total + 255) / 256, 256>>>(pos_emb, pred_emb, role_emb, w1, w2);
    }
    gemm1_kernel<<<(MAXIT / 128) * 4, 256, DYN_SMEM>>>(pred_idx, a0, a1, role_idx, is_role, b1);
    gemm2_kernel<<<(MAXIT / 128) * 2, 256, DYN_SMEM>>>(a0, a1, is_role, b2);
    dim3 g(S / 32, B);
    norm_pool_kernel<<<g, 256>>>(pos_emb, ln_g, ln_b);
    final_kernel<<<1, 256>>>(lw1, lb1, lw2, lb2, out);
}

// round 12
// speedup vs baseline: 2.0353x; 1.3708x over previous
#include <cuda_runtime.h>
#include <cuda_fp16.h>
#include <math.h>
#include <stdint.h>

#define D    256
#define DL   256
#define S    2048
#define B    8
#define F    8192
#define NE   (B * F)
#define MAXIT (2 * NE)
#define TAB_PRED 2048
#define TAB_ROLE 3072
#define TAB_ROWS 3138
#define STAGE_PITCH 132
#define MAT_BYTES 8192                      // 128 rows x 64B (k=32 fp16), packed + swizzled
#define STAGE_BYTES (2 * MAT_BYTES)         // X + W = 16384
#define NSTAGE 5
#define DYN_SMEM (NSTAGE * STAGE_BYTES + 1024)   // 82944; epilogue 67584 fits
#define SWZ(o) ((o) ^ (((o) >> 3) & 0x70))

// ---------------- device scratch ----------------
__device__ float g_agg[B * S * D];
__device__ float g_pooled[B * D];
__device__ int   g_items[MAXIT];
__device__ int   g_count;
__device__ __align__(16) __half g_tab[TAB_ROWS * 256];
__device__ __align__(16) __half g_w1t[512 * 768];   // W1^T [n][k]
__device__ __align__(16) __half g_w2t[256 * 512];   // W2^T [n][k]
__device__ __align__(16) __half g_H[(size_t)MAXIT * 512];

__device__ __forceinline__ uint32_t smem_u32_of(const void* p) {
    uint32_t a;
    asm("{ .reg .u64 t; cvta.to.shared.u64 t, %1; cvt.u32.u64 %0, t; }" : "=r"(a) : "l"(p));
    return a;
}
__device__ __forceinline__ float gelu_e(float x) { return x * normcdff(x); }

#define LDSM4(r0, r1, r2, r3, addr) \
    asm volatile("ldmatrix.sync.aligned.m8n8.x4.shared.b16 {%0,%1,%2,%3}, [%4];" \
        : "=r"(r0), "=r"(r1), "=r"(r2), "=r"(r3) : "r"(addr))

#define MMA16816(c, a, b0, b1) \
    asm volatile("mma.sync.aligned.m16n8k16.row.col.f32.f16.f16.f32 " \
        "{%0,%1,%2,%3}, {%4,%5,%6,%7}, {%8,%9}, {%0,%1,%2,%3};" \
        : "+f"((c)[0]), "+f"((c)[1]), "+f"((c)[2]), "+f"((c)[3]) \
        : "r"((a)[0]), "r"((a)[1]), "r"((a)[2]), "r"((a)[3]), "r"(b0), "r"(b1))

#define CP16(dst, src) \
    asm volatile("cp.async.cg.shared.global [%0], [%1], 16;" \
        :: "r"(dst), "l"(__cvta_generic_to_global(src)) : "memory")
#define CP_COMMIT() asm volatile("cp.async.commit_group;" ::: "memory")
#define CP_WAIT3()  asm volatile("cp.async.wait_group 3;" ::: "memory")

// ---------------- zero ----------------
__global__ void zero_kernel() {
    int i = blockIdx.x * blockDim.x + threadIdx.x;
    if (i < B * S * D) g_agg[i] = 0.0f;
    if (i < B * D)     g_pooled[i] = 0.0f;
    if (i == 0)        g_count = 0;
}

// ---------------- compact ----------------
__global__ void compact_kernel(const int* __restrict__ mask, const int* __restrict__ is_role,
                               const int* __restrict__ add_rev) {
    int e = blockIdx.x * blockDim.x + threadIdx.x;
    if (e >= NE) return;
    if (!mask[e]) return;
    bool rev = (!is_role[e]) && add_rev[e];
    int slot = atomicAdd(&g_count, rev ? 2 : 1);
    g_items[slot] = e << 1;
    if (rev) g_items[slot + 1] = (e << 1) | 1;
}

// ---------------- prep: fp16 table + fp16 W^T ----------------
__global__ void prep_kernel(const float* __restrict__ pos, const float* __restrict__ pred,
                            const float* __restrict__ role,
                            const float* __restrict__ w1, const float* __restrict__ w2) {
    int tid = blockIdx.x * blockDim.x + threadIdx.x;
    const int NTAB = TAB_ROWS * 256;
    const int NW1 = 512 * 768;
    const int NW2 = 256 * 512;
    if (tid < NTAB) {
        int row = tid >> 8, col = tid & 255;
        float v;
        if (row < TAB_PRED)      v = pos[tid];
        else if (row < TAB_ROLE) v = pred[(row - TAB_PRED) * 256 + col];
        else                     v = role[(row - TAB_ROLE) * 256 + col];
        g_tab[tid] = __float2half(v);
    } else if (tid < NTAB + NW1) {
        int u = tid - NTAB;                    // u = n*768 + k
        int n = u / 768, k = u - n * 768;
        g_w1t[u] = __float2half(w1[(size_t)k * 512 + n]);
    } else if (tid < NTAB + NW1 + NW2) {
        int u = tid - NTAB - NW1;              // u = n*512 + k
        int n = u / 512, k = u - n * 512;
        g_w2t[u] = __float2half(w2[(size_t)k * 256 + n]);
    }
}

// ---------------- GEMM1: X[128x768] @ W1[768x512] -> gelu -> g_H ----------------
// grid = tiles x 4 n-quarters; 5-stage cp.async, single-pass fp16
__global__ void __launch_bounds__(256, 2)
gemm1_kernel(const int* __restrict__ pred_idx,
             const int* __restrict__ a0, const int* __restrict__ a1,
             const int* __restrict__ role_idx, const int* __restrict__ is_role,
             const float* __restrict__ b1) {
    extern __shared__ char smraw[];
    __shared__ int ssrc[128][3];

    int t = threadIdx.x;
    int tile = blockIdx.x >> 2, nq = blockIdx.x & 3;
    int count = g_count;
    int base = tile * 128;
    if (base >= count) return;
    int nE = min(128, count - base);

    if (t < 128) {
        int r0 = 0, r1 = TAB_PRED, r2 = 0;
        if (t < nE) {
            int item = g_items[base + t];
            int e = item >> 1, dir = item & 1;
            int i0 = a0[e], i1 = a1[e];
            r1 = TAB_PRED + pred_idx[e];
            if (dir == 0) {
                int rr = is_role[e];
                r0 = i0;
                r2 = rr ? (TAB_ROLE + role_idx[e]) : i1;
            } else { r0 = i1; r2 = i0; }
        }
        ssrc[t][0] = r0; ssrc[t][1] = r1; ssrc[t][2] = r2;
    }

    uint32_t raw = smem_u32_of(smraw);
    uint32_t smu = (raw + 1023u) & ~1023u;
    __syncthreads();

    int w = t >> 5, lane = t & 31;
    int wm = w >> 1, wn = w & 1;
    int blk = lane >> 3, brow = lane & 7;

    float acc[64];
    #pragma unroll
    for (int i = 0; i < 64; i++) acc[i] = 0.0f;

    const int KC = 24;  // 768 / 32

    // fill: X chunk (512 cp), W chunk (512 cp)
    #define G1_FILL(kc_, st_) do { \
        uint32_t sb = smu + (st_) * STAGE_BYTES; \
        int seg_ = (kc_) >> 3; \
        int innb_ = ((kc_) & 7) * 64; \
        _Pragma("unroll") \
        for (int i = t; i < 512; i += 256) { \
            int e_ = i >> 2, q_ = i & 3; \
            const char* src_ = (const char*)g_tab \
                               + (size_t)ssrc[e_][seg_] * 512 + innb_ + q_ * 16; \
            CP16(sb + SWZ(e_ * 64 + q_ * 16), src_); \
        } \
        _Pragma("unroll") \
        for (int i = t; i < 512; i += 256) { \
            int r_ = i >> 2, q_ = i & 3; \
            const char* src_ = (const char*)g_w1t \
                               + (size_t)(nq * 128 + r_) * 1536 + (kc_) * 64 + q_ * 16; \
            CP16(sb + MAT_BYTES + SWZ(r_ * 64 + q_ * 16), src_); \
        } \
    } while (0)

    G1_FILL(0, 0); CP_COMMIT();
    G1_FILL(1, 1); CP_COMMIT();
    G1_FILL(2, 2); CP_COMMIT();
    G1_FILL(3, 3); CP_COMMIT();

    int st = 0;                 // stage of current chunk
    int stn = 4;                // stage to fill next (kc+4)
    for (int kc = 0; kc < KC; kc++) {
        CP_WAIT3();
        __syncthreads();        // all warps done with MMA(kc-1) => stage stn safe
        if (kc + 4 < KC) G1_FILL(kc + 4, stn);
        CP_COMMIT();

        uint32_t sb = smu + st * STAGE_BYTES;
        uint32_t xh_u = sb;
        uint32_t wh_u = sb + MAT_BYTES;

        #pragma unroll
        for (int kk = 0; kk < 2; kk++) {
            uint32_t ah[2][4];
            #pragma unroll
            for (int mf = 0; mf < 2; mf++) {
                uint32_t off = SWZ((uint32_t)(wm * 32 + mf * 16 + (blk & 1) * 8 + brow) * 64
                                   + kk * 32 + (blk >> 1) * 16);
                LDSM4(ah[mf][0], ah[mf][1], ah[mf][2], ah[mf][3], xh_u + off);
            }
            #pragma unroll
            for (int nf2 = 0; nf2 < 4; nf2++) {
                uint32_t boff = SWZ((uint32_t)(wn * 64 + nf2 * 16 + (blk >> 1) * 8 + brow) * 64
                                    + kk * 32 + (blk & 1) * 16);
                uint32_t bh[4];
                LDSM4(bh[0], bh[1], bh[2], bh[3], wh_u + boff);
                float* c0 = &acc[(nf2 * 2) * 4];
                float* c1 = &acc[(nf2 * 2 + 1) * 4];
                float* c2 = &acc[(8 + nf2 * 2) * 4];
                float* c3 = &acc[(8 + nf2 * 2 + 1) * 4];
                MMA16816(c0, ah[0], bh[0], bh[1]);
                MMA16816(c1, ah[0], bh[2], bh[3]);
                MMA16816(c2, ah[1], bh[0], bh[1]);
                MMA16816(c3, ah[1], bh[2], bh[3]);
            }
        }
        st = (st + 1 == NSTAGE) ? 0 : st + 1;
        stn = (stn + 1 == NSTAGE) ? 0 : stn + 1;
    }
    __syncthreads();

    // stage accumulators -> bias+gelu -> g_H (fp16)
    float* stage = (float*)smraw;
    int g = lane >> 2, i2 = (lane & 3) * 2;
    #pragma unroll
    for (int mf = 0; mf < 2; mf++)
        #pragma unroll
        for (int nf = 0; nf < 8; nf++) {
            float* c = &acc[(mf * 8 + nf) * 4];
            int r = wm * 32 + mf * 16 + g;
            int col = wn * 64 + nf * 8 + i2;
            stage[r * STAGE_PITCH + col]     = c[0];
            stage[r * STAGE_PITCH + col + 1] = c[1];
            stage[(r + 8) * STAGE_PITCH + col]     = c[2];
            stage[(r + 8) * STAGE_PITCH + col + 1] = c[3];
        }
    __syncthreads();
    {
        int col = t & 127, eh = t >> 7;
        float bias = b1[nq * 128 + col];
        for (int e = eh; e < nE; e += 2) {
            float x = stage[e * STAGE_PITCH + col] + bias;
            g_H[(size_t)(base + e) * 512 + nq * 128 + col] = __float2half(gelu_e(x));
        }
    }
}

// ---------------- GEMM2: H[128x512] @ W2[512x256] -> +b2 -> atomic scatter ----------------
__global__ void __launch_bounds__(256, 2)
gemm2_kernel(const int* __restrict__ a0, const int* __restrict__ a1,
             const int* __restrict__ is_role, const float* __restrict__ b2) {
    extern __shared__ char smraw[];
    __shared__ int stgt[128];

    int t = threadIdx.x;
    int tile = blockIdx.x >> 1, nq = blockIdx.x & 1;
    int count = g_count;
    int base = tile * 128;
    if (base >= count) return;
    int nE = min(128, count - base);

    if (t < 128) {
        int tg = 0, bidx = 0;
        if (t < nE) {
            int item = g_items[base + t];
            int e = item >> 1, dir = item & 1;
            bidx = e >> 13;
            int i0 = a0[e], i1 = a1[e];
            if (dir == 0) { int rr = is_role[e]; tg = rr ? i0 : i1; }
            else tg = i0;
        }
        stgt[t] = (bidx * S + tg) * D;
    }

    uint32_t raw = smem_u32_of(smraw);
    uint32_t smu = (raw + 1023u) & ~1023u;
    __syncthreads();

    int w = t >> 5, lane = t & 31;
    int wm = w >> 1, wn = w & 1;
    int blk = lane >> 3, brow = lane & 7;

    float acc[64];
    #pragma unroll
    for (int i = 0; i < 64; i++) acc[i] = 0.0f;

    const int KC = 16;  // 512 / 32

    #define G2_FILL(kc_, st_) do { \
        uint32_t sb = smu + (st_) * STAGE_BYTES; \
        _Pragma("unroll") \
        for (int i = t; i < 512; i += 256) { \
            int e_ = i >> 2, q_ = i & 3; \
            const char* src_ = (const char*)g_H \
                               + (size_t)(base + e_) * 1024 + (kc_) * 64 + q_ * 16; \
            CP16(sb + SWZ(e_ * 64 + q_ * 16), src_); \
        } \
        _Pragma("unroll") \
        for (int i = t; i < 512; i += 256) { \
            int r_ = i >> 2, q_ = i & 3; \
            const char* src_ = (const char*)g_w2t \
                               + (size_t)(nq * 128 + r_) * 1024 + (kc_) * 64 + q_ * 16; \
            CP16(sb + MAT_BYTES + SWZ(r_ * 64 + q_ * 16), src_); \
        } \
    } while (0)

    G2_FILL(0, 0); CP_COMMIT();
    G2_FILL(1, 1); CP_COMMIT();
    G2_FILL(2, 2); CP_COMMIT();
    G2_FILL(3, 3); CP_COMMIT();

    int st = 0, stn = 4;
    for (int kc = 0; kc < KC; kc++) {
        CP_WAIT3();
        __syncthreads();
        if (kc + 4 < KC) G2_FILL(kc + 4, stn);
        CP_COMMIT();

        uint32_t sb = smu + st * STAGE_BYTES;
        uint32_t xh_u = sb;
        uint32_t wh_u = sb + MAT_BYTES;

        #pragma unroll
        for (int kk = 0; kk < 2; kk++) {
            uint32_t ah[2][4];
            #pragma unroll
            for (int mf = 0; mf < 2; mf++) {
                uint32_t off = SWZ((uint32_t)(wm * 32 + mf * 16 + (blk & 1) * 8 + brow) * 64
                                   + kk * 32 + (blk >> 1) * 16);
                LDSM4(ah[mf][0], ah[mf][1], ah[mf][2], ah[mf][3], xh_u + off);
            }
            #pragma unroll
            for (int nf2 = 0; nf2 < 4; nf2++) {
                uint32_t boff = SWZ((uint32_t)(wn * 64 + nf2 * 16 + (blk >> 1) * 8 + brow) * 64
                                    + kk * 32 + (blk & 1) * 16);
                uint32_t bh[4];
                LDSM4(bh[0], bh[1], bh[2], bh[3], wh_u + boff);
                float* c0 = &acc[(nf2 * 2) * 4];
                float* c1 = &acc[(nf2 * 2 + 1) * 4];
                float* c2 = &acc[(8 + nf2 * 2) * 4];
                float* c3 = &acc[(8 + nf2 * 2 + 1) * 4];
                MMA16816(c0, ah[0], bh[0], bh[1]);
                MMA16816(c1, ah[0], bh[2], bh[3]);
                MMA16816(c2, ah[1], bh[0], bh[1]);
                MMA16816(c3, ah[1], bh[2], bh[3]);
            }
        }
        st = (st + 1 == NSTAGE) ? 0 : st + 1;
        stn = (stn + 1 == NSTAGE) ? 0 : stn + 1;
    }
    __syncthreads();

    float* stage = (float*)smraw;
    int g = lane >> 2, i2 = (lane & 3) * 2;
    #pragma unroll
    for (int mf = 0; mf < 2; mf++)
        #pragma unroll
        for (int nf = 0; nf < 8; nf++) {
            float* c = &acc[(mf * 8 + nf) * 4];
            int r = wm * 32 + mf * 16 + g;
            int col = wn * 64 + nf * 8 + i2;
            stage[r * STAGE_PITCH + col]     = c[0];
            stage[r * STAGE_PITCH + col + 1] = c[1];
            stage[(r + 8) * STAGE_PITCH + col]     = c[2];
            stage[(r + 8) * STAGE_PITCH + col + 1] = c[3];
        }
    __syncthreads();
    {
        int col = t & 127, eh = t >> 7;
        float bias = b2[nq * 128 + col];
        for (int e = eh; e < nE; e += 2)
            atomicAdd(&g_agg[stgt[e] + nq * 128 + col],
                      stage[e * STAGE_PITCH + col] + bias);
    }
}

// ---------------- layernorm + pooled mean ----------------
__global__ void norm_pool_kernel(const float* __restrict__ pos,
                                 const float* __restrict__ ln_g,
                                 const float* __restrict__ ln_b) {
    int b = blockIdx.y;
    int s_base = blockIdx.x * 32;
    int warp = threadIdx.x >> 5, lane = threadIdx.x & 31;
    float gg[8], be[8], pacc[8];
    #pragma unroll
    for (int i = 0; i < 8; i++) {
        gg[i] = ln_g[i * 32 + lane]; be[i] = ln_b[i * 32 + lane]; pacc[i] = 0.0f;
    }
    for (int r = warp; r < 32; r += 8) {
        int ss = s_base + r;
        const float* ag = &g_agg[((size_t)b * S + ss) * D];
        const float* ps = &pos[(size_t)ss * D];
        float x[8]; float sum = 0.0f;
        #pragma unroll
        for (int i = 0; i < 8; i++) { x[i] = ps[i * 32 + lane] + ag[i * 32 + lane]; sum += x[i]; }
        #pragma unroll
        for (int off = 16; off > 0; off >>= 1) sum += __shfl_xor_sync(0xFFFFFFFFu, sum, off);
        float mu = sum * (1.0f / D); float v = 0.0f;
        #pragma unroll
        for (int i = 0; i < 8; i++) { x[i] -= mu; v += x[i] * x[i]; }
        #pragma unroll
        for (int off = 16; off > 0; off >>= 1) v += __shfl_xor_sync(0xFFFFFFFFu, v, off);
        float inv = rsqrtf(v * (1.0f / D) + 1e-5f);
        #pragma unroll
        for (int i = 0; i < 8; i++) pacc[i] += x[i] * inv * gg[i] + be[i];
    }
    __shared__ float sp[256];
    sp[threadIdx.x] = 0.0f;
    __syncthreads();
    #pragma unroll
    for (int i = 0; i < 8; i++) atomicAdd(&sp[i * 32 + lane], pacc[i]);
    __syncthreads();
    atomicAdd(&g_pooled[b * D + threadIdx.x], sp[threadIdx.x] * (1.0f / S));
}

// ---------------- final small MLP ----------------
__global__ void final_kernel(const float* __restrict__ lw1, const float* __restrict__ lb1,
                             const float* __restrict__ lw2, const float* __restrict__ lb2,
                             float* __restrict__ out) {
    __shared__ float P[B * D];
    __shared__ float Hh[B * DL];
    int t = threadIdx.x;
    for (int i = t; i < B * D; i += 256) P[i] = g_pooled[i];
    __syncthreads();
    float a[B];
    #pragma unroll
    for (int b = 0; b < B; b++) a[b] = lb1[t];
    for (int k = 0; k < D; k++) {
        float wv = lw1[k * DL + t];
        #pragma unroll
        for (int b = 0; b < B; b++) a[b] = fmaf(P[b * D + k], wv, a[b]);
    }
    #pragma unroll
    for (int b = 0; b < B; b++) Hh[b * DL + t] = gelu_e(a[b]);
    __syncthreads();
    #pragma unroll
    for (int b = 0; b < B; b++) a[b] = lb2[t];
    for (int k = 0; k < DL; k++) {
        float wv = lw2[k * DL + t];
        #pragma unroll
        for (int b = 0; b < B; b++) a[b] = fmaf(Hh[b * DL + k], wv, a[b]);
    }
    #pragma unroll
    for (int b = 0; b < B; b++) out[b * DL + t] = a[b];
}

// ---------------- launch ----------------
extern "C" void kernel_launch(void* const* d_in, const int* in_sizes, int n_in,
                              void* d_out, int out_size) {
    const float* pos_emb  = (const float*)d_in[0];
    const float* pred_emb = (const float*)d_in[1];
    const float* role_emb = (const float*)d_in[2];
    const float* w1       = (const float*)d_in[3];
    const float* b1       = (const float*)d_in[4];
    const float* w2       = (const float*)d_in[5];
    const float* b2       = (const float*)d_in[6];
    const float* ln_g     = (const float*)d_in[7];
    const float* ln_b     = (const float*)d_in[8];
    const float* lw1      = (const float*)d_in[9];
    const float* lb1      = (const float*)d_in[10];
    const float* lw2      = (const float*)d_in[11];
    const float* lb2      = (const float*)d_in[12];
    const int* pred_idx   = (const int*)d_in[13];
    const int* a0         = (const int*)d_in[14];
    const int* a1         = (const int*)d_in[15];
    const int* role_idx   = (const int*)d_in[16];
    const int* is_role    = (const int*)d_in[17];
    const int* add_rev    = (const int*)d_in[18];
    const int* mask       = (const int*)d_in[19];
    float* out = (float*)d_out;

    cudaFuncSetAttribute(gemm1_kernel, cudaFuncAttributeMaxDynamicSharedMemorySize, DYN_SMEM);
    cudaFuncSetAttribute(gemm2_kernel, cudaFuncAttributeMaxDynamicSharedMemorySize, DYN_SMEM);

    zero_kernel<<<(B * S * D + 255) / 256, 256>>>();
    compact_kernel<<<(NE + 255) / 256, 256>>>(mask, is_role, add_rev);
    {
        int total = TAB_ROWS * 256 + 512 * 768 + 256 * 512;
        prep_kernel<<<(total + 255) / 256, 256>>>(pos_emb, pred_emb, role_emb, w1, w2);
    }
    gemm1_kernel<<<(MAXIT / 128) * 4, 256, DYN_SMEM>>>(pred_idx, a0, a1, role_idx, is_role, b1);
    gemm2_kernel<<<(MAXIT / 128) * 2, 256, DYN_SMEM>>>(a0, a1, is_role, b2);
    dim3 g(S / 32, B);
    norm_pool_kernel<<<g, 256>>>(pos_emb, ln_g, ln_b);
    final_kernel<<<1, 256>>>(lw1, lb1, lw2, lb2, out);
}